// round 4
// baseline (speedup 1.0000x reference)
#include <cuda_runtime.h>
#include <cuda_bf16.h>

// ---------------------------------------------------------------------------
// GaussianVoxelizer round 4: 2 launches
//   k_prepbin: warp/gaussian, lane0 math, lane-per-tile-slot atomics.
//   k_main:    2 blocks per tile (feature halves 0-15 / 16-31), 256 thr,
//              2 voxels per thread (z, z+4), 32-reg accumulators -> occ 3x.
// ---------------------------------------------------------------------------

#define NG      8192
#define HN      160
#define WN      160
#define DN      16
#define VSZ     0.4f
#define VMX     (-32.0f)
#define VMY     (-32.0f)
#define VMZ     (-1.0f)

#define TSH     3
#define TXN     (HN >> TSH)         // 20
#define TYN     (WN >> TSH)         // 20
#define TZN     (DN >> TSH)         // 2
#define NTILES  (TXN * TYN * TZN)   // 800

#define TCAP    256
#define CCHUNK  128
#define KEXP2   0.72134752044448170f   // 0.5 * log2(e)

__device__ float g_params[NG * 16];
__device__ int   g_cnt[NTILES];        // zero-init at load; k_main re-zeros
__device__ int   g_list[NTILES * TCAP];

__device__ __forceinline__ float ex2(float x) {
    float r;
    asm("ex2.approx.f32 %0, %1;" : "=f"(r) : "f"(x));
    return r;
}

// ---------------------------------------------------------------------------
__global__ void k_prepbin(const float* __restrict__ means,
                          const float* __restrict__ opac,
                          const float* __restrict__ scl,
                          const float* __restrict__ rot) {
    int t = blockIdx.x * blockDim.x + threadIdx.x;
    int g = t >> 5, lane = t & 31;
    if (g >= NG) return;

    unsigned range = 0xFFFFFFFFu;
    if (lane == 0) {
        float qw = rot[4 * g + 0], qx = rot[4 * g + 1];
        float qy = rot[4 * g + 2], qz = rot[4 * g + 3];
        float qn = rsqrtf(qw * qw + qx * qx + qy * qy + qz * qz);
        qw *= qn; qx *= qn; qy *= qn; qz *= qn;

        float r00 = 1.f - 2.f * (qy * qy + qz * qz);
        float r01 = 2.f * (qx * qy - qw * qz);
        float r02 = 2.f * (qx * qz + qw * qy);
        float r10 = 2.f * (qx * qy + qw * qz);
        float r11 = 1.f - 2.f * (qx * qx + qz * qz);
        float r12 = 2.f * (qy * qz - qw * qx);
        float r20 = 2.f * (qx * qz - qw * qy);
        float r21 = 2.f * (qy * qz + qw * qx);
        float r22 = 1.f - 2.f * (qx * qx + qy * qy);

        float s0 = scl[3 * g + 0], s1 = scl[3 * g + 1], s2 = scl[3 * g + 2];
        float v0 = s0 * s0, v1 = s1 * s1, v2 = s2 * s2;
        float a0 = 1.f / v0, a1 = 1.f / v1, a2 = 1.f / v2;

        float i00 = (r00 * r00 * a0 + r01 * r01 * a1 + r02 * r02 * a2) * KEXP2;
        float i01 = (r00 * r10 * a0 + r01 * r11 * a1 + r02 * r12 * a2) * KEXP2;
        float i02 = (r00 * r20 * a0 + r01 * r21 * a1 + r02 * r22 * a2) * KEXP2;
        float i11 = (r10 * r10 * a0 + r11 * r11 * a1 + r12 * r12 * a2) * KEXP2;
        float i12 = (r10 * r20 * a0 + r11 * r21 * a1 + r12 * r22 * a2) * KEXP2;
        float i22 = (r20 * r20 * a0 + r21 * r21 * a1 + r22 * r22 * a2) * KEXP2;

        float c00 = r00 * r00 * v0 + r01 * r01 * v1 + r02 * r02 * v2;
        float c11 = r10 * r10 * v0 + r11 * r11 * v1 + r12 * r12 * v2;
        float c22 = r20 * r20 * v0 + r21 * r21 * v1 + r22 * r22 * v2;
        float bx = 3.f * sqrtf(c00);
        float by = 3.f * sqrtf(c11);
        float bz = 3.f * sqrtf(c22);

        float mx = means[3 * g + 0], my = means[3 * g + 1], mz = means[3 * g + 2];
        float op = opac[g];

        float4* p4 = (float4*)&g_params[g * 16];
        p4[0] = make_float4(mx, my, mz, op);
        p4[1] = make_float4(bx, by, bz, 0.f);
        p4[2] = make_float4(i00, i01, i02, i11);
        p4[3] = make_float4(i12, i22, 0.f, 0.f);

        float mu[3] = { mx, my, mz };
        float bb[3] = { bx, by, bz };
        const float vmin[3] = { VMX, VMY, VMZ };
        const int nd[3] = { HN, WN, DN };
        int lo[3], hi[3];
        bool ok = true;
#pragma unroll
        for (int d = 0; d < 3; d++) {
            float l = (mu[d] - bb[d] - vmin[d]) / VSZ - 0.5f;
            float h = (mu[d] + bb[d] - vmin[d]) / VSZ - 0.5f;
            int i0 = (int)ceilf(l - 1e-3f);  if (i0 < 0) i0 = 0;
            int i1 = (int)floorf(h + 1e-3f); if (i1 > nd[d] - 1) i1 = nd[d] - 1;
            if (i0 > i1) ok = false;
            lo[d] = i0 >> TSH; hi[d] = i1 >> TSH;
        }
        if (ok)
            range = (unsigned)lo[0] | ((unsigned)hi[0] << 5)
                  | ((unsigned)lo[1] << 10) | ((unsigned)hi[1] << 15)
                  | ((unsigned)lo[2] << 20) | ((unsigned)hi[2] << 25);
    }
    range = __shfl_sync(0xffffffffu, range, 0);
    if (range == 0xFFFFFFFFu) return;

    int x0 = range & 31, x1 = (range >> 5) & 31;
    int y0 = (range >> 10) & 31, y1 = (range >> 15) & 31;
    int z0 = (range >> 20) & 31, z1 = (range >> 25) & 31;
    int nx = x1 - x0 + 1, ny = y1 - y0 + 1, nz = z1 - z0 + 1;
    if (lane >= nx * ny * nz) return;       // max span 3*3*2 = 18 <= 32
    int sz = lane % nz; int rem = lane / nz;
    int sy = rem % ny;  int sx = rem / ny;
    int tile = ((x0 + sx) * TYN + (y0 + sy)) * TZN + (z0 + sz);
    int pos = atomicAdd(&g_cnt[tile], 1);
    if (pos < TCAP) g_list[tile * TCAP + pos] = g;
}

// ---------------------------------------------------------------------------
// 2 blocks per tile: block handles feature channels [fh*16, fh*16+16)
__global__ __launch_bounds__(256, 3)
void k_main(const float* __restrict__ feat, float* __restrict__ out) {
    __shared__ int    s_idx[CCHUNK];
    __shared__ float4 s_par[CCHUNK * 4];
    __shared__ float4 s_fea[CCHUNK * 4];   // 16 features = 4 float4

    int b = blockIdx.x;
    int fh = b & 1;                        // feature half
    int bt = b >> 1;
    int tz = bt % TZN;
    int ty = (bt / TZN) % TYN;
    int tx = bt / (TZN * TYN);

    int tid = threadIdx.x;
    int lk = tid & 3;                      // z: lk and lk+4
    int lj = (tid >> 2) & 7;
    int li = tid >> 5;

    int vi = (tx << TSH) + li;
    int vj = (ty << TSH) + lj;
    int vk = (tz << TSH) + lk;

    float px  = ((float)vi + 0.5f) * VSZ + VMX;
    float py  = ((float)vj + 0.5f) * VSZ + VMY;
    float pz0 = ((float)vk + 0.5f) * VSZ + VMZ;
    float pz1 = pz0 + 4.f * VSZ;

    float4 a0[4], a1[4];
#pragma unroll
    for (int r = 0; r < 4; r++) {
        a0[r] = make_float4(0.f, 0.f, 0.f, 0.f);
        a1[r] = make_float4(0.f, 0.f, 0.f, 0.f);
    }

    int tile = (tx * TYN + ty) * TZN + tz;
    int n = min(g_cnt[tile], TCAP);

    const float4* gp4 = (const float4*)g_params;
    const float4* gf4 = (const float4*)feat;

    for (int base = 0; base < n; base += CCHUNK) {
        int cnt = min(CCHUNK, n - base);
        __syncthreads();
        if (tid < cnt) s_idx[tid] = g_list[tile * TCAP + base + tid];
        __syncthreads();
        for (int u = tid; u < cnt * 4; u += 256) {
            int c = u >> 2, pc = u & 3;
            int gi = s_idx[c];
            s_par[u] = gp4[gi * 4 + pc];
            s_fea[u] = gf4[gi * 8 + fh * 4 + pc];
        }
        __syncthreads();

        for (int c = 0; c < cnt; c++) {
            float4 p0 = s_par[c * 4 + 0];
            float4 p1 = s_par[c * 4 + 1];
            float dx = px - p0.x, dy = py - p0.y;
            float dz0 = pz0 - p0.z, dz1 = pz1 - p0.z;
            bool inxy = (fabsf(dx) <= p1.x) && (fabsf(dy) <= p1.y);
            bool in0 = inxy && (fabsf(dz0) <= p1.z);
            bool in1 = inxy && (fabsf(dz1) <= p1.z);
            if (in0 || in1) {
                float4 p2 = s_par[c * 4 + 2];
                float4 p3 = s_par[c * 4 + 3];
                // quadratic pre-scaled by 0.5*log2(e)
                float mb = dx * (p2.x * dx + 2.f * p2.y * dy) + p2.w * dy * dy;
                float cz = 2.f * (p2.z * dx + p3.x * dy);
                float m0 = mb + dz0 * (p3.y * dz0 + cz);
                float m1 = mb + dz1 * (p3.y * dz1 + cz);
                float w0 = in0 ? p0.w * ex2(-m0) : 0.f;
                float w1 = in1 ? p0.w * ex2(-m1) : 0.f;
                const float4* f = &s_fea[c * 4];
#pragma unroll
                for (int r = 0; r < 4; r++) {
                    float4 fv = f[r];
                    a0[r].x += w0 * fv.x; a0[r].y += w0 * fv.y;
                    a0[r].z += w0 * fv.z; a0[r].w += w0 * fv.w;
                    a1[r].x += w1 * fv.x; a1[r].y += w1 * fv.y;
                    a1[r].z += w1 * fv.z; a1[r].w += w1 * fv.w;
                }
            }
        }
    }

    long long v0 = ((long long)vi * WN + vj) * DN + vk;
    float4* o0 = (float4*)(out + v0 * 32 + fh * 16);
    float4* o1 = (float4*)(out + (v0 + 4) * 32 + fh * 16);
#pragma unroll
    for (int r = 0; r < 4; r++) o0[r] = a0[r];
#pragma unroll
    for (int r = 0; r < 4; r++) o1[r] = a1[r];

    // reset this tile's counter for next graph replay (one block of the pair)
    __syncthreads();
    if (tid == 0 && fh == 0) g_cnt[tile] = 0;
}

// ---------------------------------------------------------------------------
extern "C" void kernel_launch(void* const* d_in, const int* in_sizes, int n_in,
                              void* d_out, int out_size) {
    const float* means = (const float*)d_in[0];
    const float* opac  = (const float*)d_in[1];
    const float* scl   = (const float*)d_in[2];
    const float* rot   = (const float*)d_in[3];
    const float* feat  = (const float*)d_in[4];
    float* out = (float*)d_out;

    k_prepbin<<<(NG * 32 + 255) / 256, 256>>>(means, opac, scl, rot);
    k_main<<<NTILES * 2, 256>>>(feat, out);
}

// round 5
// speedup vs baseline: 1.0169x; 1.0169x over previous
#include <cuda_runtime.h>
#include <cuda_bf16.h>

// ---------------------------------------------------------------------------
// GaussianVoxelizer round 5: fine tiles + packed f32x2 FMA
//   Tiles: 4x4x4 voxels (40x40x4 = 6400), ONE WARP per tile, 2 z-voxels/thread.
//   Inner loop uses fma.rn.f32x2 -> 32 issues for 64 MACs per candidate.
//   Warp-synchronous smem staging (no block barriers). Counter reset folded
//   into the lane-0 count read.
// ---------------------------------------------------------------------------

#define NG      8192
#define HN      160
#define WN      160
#define DN      16
#define VSZ     0.4f
#define VMX     (-32.0f)
#define VMY     (-32.0f)
#define VMZ     (-1.0f)

#define TSH     2                   // 4 voxels per tile per dim
#define TXN     (HN >> TSH)         // 40
#define TYN     (WN >> TSH)         // 40
#define TZN     (DN >> TSH)         // 4
#define NTILES  (TXN * TYN * TZN)   // 6400

#define TCAP    192
#define KEXP2   0.72134752044448170f   // 0.5 * log2(e)

__device__ float g_params[NG * 16];
__device__ int   g_cnt[NTILES];        // zero at load; k_main re-zeros each run
__device__ int   g_list[NTILES * TCAP];

__device__ __forceinline__ float ex2(float x) {
    float r;
    asm("ex2.approx.f32 %0, %1;" : "=f"(r) : "f"(x));
    return r;
}
__device__ __forceinline__ unsigned long long fma2(unsigned long long a,
                                                   unsigned long long b,
                                                   unsigned long long c) {
    unsigned long long d;
    asm("fma.rn.f32x2 %0, %1, %2, %3;" : "=l"(d) : "l"(a), "l"(b), "l"(c));
    return d;
}
__device__ __forceinline__ unsigned long long pack2(float x) {
    unsigned long long d;
    unsigned u = __float_as_uint(x);
    asm("mov.b64 %0, {%1, %1};" : "=l"(d) : "r"(u));
    return d;
}

// ---------------------------------------------------------------------------
__global__ void k_prepbin(const float* __restrict__ means,
                          const float* __restrict__ opac,
                          const float* __restrict__ scl,
                          const float* __restrict__ rot) {
    int t = blockIdx.x * blockDim.x + threadIdx.x;
    int g = t >> 5, lane = t & 31;
    if (g >= NG) return;

    unsigned lo_pack = 0, n_pack = 0;   // n_pack==0 => empty
    if (lane == 0) {
        float qw = rot[4 * g + 0], qx = rot[4 * g + 1];
        float qy = rot[4 * g + 2], qz = rot[4 * g + 3];
        float qn = rsqrtf(qw * qw + qx * qx + qy * qy + qz * qz);
        qw *= qn; qx *= qn; qy *= qn; qz *= qn;

        float r00 = 1.f - 2.f * (qy * qy + qz * qz);
        float r01 = 2.f * (qx * qy - qw * qz);
        float r02 = 2.f * (qx * qz + qw * qy);
        float r10 = 2.f * (qx * qy + qw * qz);
        float r11 = 1.f - 2.f * (qx * qx + qz * qz);
        float r12 = 2.f * (qy * qz - qw * qx);
        float r20 = 2.f * (qx * qz - qw * qy);
        float r21 = 2.f * (qy * qz + qw * qx);
        float r22 = 1.f - 2.f * (qx * qx + qy * qy);

        float s0 = scl[3 * g + 0], s1 = scl[3 * g + 1], s2 = scl[3 * g + 2];
        float v0 = s0 * s0, v1 = s1 * s1, v2 = s2 * s2;
        float a0 = 1.f / v0, a1 = 1.f / v1, a2 = 1.f / v2;

        float i00 = (r00 * r00 * a0 + r01 * r01 * a1 + r02 * r02 * a2) * KEXP2;
        float i01 = (r00 * r10 * a0 + r01 * r11 * a1 + r02 * r12 * a2) * KEXP2;
        float i02 = (r00 * r20 * a0 + r01 * r21 * a1 + r02 * r22 * a2) * KEXP2;
        float i11 = (r10 * r10 * a0 + r11 * r11 * a1 + r12 * r12 * a2) * KEXP2;
        float i12 = (r10 * r20 * a0 + r11 * r21 * a1 + r12 * r22 * a2) * KEXP2;
        float i22 = (r20 * r20 * a0 + r21 * r21 * a1 + r22 * r22 * a2) * KEXP2;

        float c00 = r00 * r00 * v0 + r01 * r01 * v1 + r02 * r02 * v2;
        float c11 = r10 * r10 * v0 + r11 * r11 * v1 + r12 * r12 * v2;
        float c22 = r20 * r20 * v0 + r21 * r21 * v1 + r22 * r22 * v2;
        float bx = 3.f * sqrtf(c00);
        float by = 3.f * sqrtf(c11);
        float bz = 3.f * sqrtf(c22);

        float mx = means[3 * g + 0], my = means[3 * g + 1], mz = means[3 * g + 2];
        float op = opac[g];

        float4* p4 = (float4*)&g_params[g * 16];
        p4[0] = make_float4(mx, my, mz, op);
        p4[1] = make_float4(bx, by, bz, 0.f);
        p4[2] = make_float4(i00, i01, i02, i11);
        p4[3] = make_float4(i12, i22, 0.f, 0.f);

        float mu[3] = { mx, my, mz };
        float bb[3] = { bx, by, bz };
        const float vmin[3] = { VMX, VMY, VMZ };
        const int nd[3] = { HN, WN, DN };
        int lo[3], nn[3];
        bool ok = true;
#pragma unroll
        for (int d = 0; d < 3; d++) {
            float l = (mu[d] - bb[d] - vmin[d]) / VSZ - 0.5f;
            float h = (mu[d] + bb[d] - vmin[d]) / VSZ - 0.5f;
            int i0 = (int)ceilf(l - 1e-3f);  if (i0 < 0) i0 = 0;
            int i1 = (int)floorf(h + 1e-3f); if (i1 > nd[d] - 1) i1 = nd[d] - 1;
            if (i0 > i1) ok = false;
            lo[d] = i0 >> TSH;
            nn[d] = (i1 >> TSH) - (i0 >> TSH) + 1;
        }
        if (ok) {
            lo_pack = (unsigned)lo[0] | ((unsigned)lo[1] << 8) | ((unsigned)lo[2] << 16);
            n_pack  = (unsigned)nn[0] | ((unsigned)nn[1] << 8) | ((unsigned)nn[2] << 16);
        }
    }
    lo_pack = __shfl_sync(0xffffffffu, lo_pack, 0);
    n_pack  = __shfl_sync(0xffffffffu, n_pack, 0);
    if (n_pack == 0) return;

    int x0 = lo_pack & 255, y0 = (lo_pack >> 8) & 255, z0 = (lo_pack >> 16) & 255;
    int nx = n_pack & 255, ny = (n_pack >> 8) & 255, nz = (n_pack >> 16) & 255;
    int total = nx * ny * nz;              // <= ~100
    for (int s = lane; s < total; s += 32) {
        int sz = s % nz; int rem = s / nz;
        int sy = rem % ny; int sx = rem / ny;
        int tile = ((x0 + sx) * TYN + (y0 + sy)) * TZN + (z0 + sz);
        int pos = atomicAdd(&g_cnt[tile], 1);
        if (pos < TCAP) g_list[tile * TCAP + pos] = g;
    }
}

// ---------------------------------------------------------------------------
// one warp per 4x4x4 tile; thread = (lx,ly) xy cell + 2 contiguous z voxels
__global__ __launch_bounds__(128, 4)
void k_main(const float* __restrict__ feat, float* __restrict__ out) {
    __shared__ float4     s_par[4][32][4];
    __shared__ ulonglong2 s_fea[4][32][8];

    int wid  = threadIdx.x >> 5;
    int lane = threadIdx.x & 31;
    int tile = blockIdx.x * 4 + wid;

    int tz = tile & (TZN - 1);
    int ty = (tile >> 2) % TYN;
    int tx = tile / (TZN * TYN);

    int lh = lane & 1;
    int ly = (lane >> 1) & 3;
    int lx = lane >> 3;

    int vi = (tx << TSH) + lx;
    int vj = (ty << TSH) + ly;
    int vk = (tz << TSH) + (lh << 1);

    float px  = ((float)vi + 0.5f) * VSZ + VMX;
    float py  = ((float)vj + 0.5f) * VSZ + VMY;
    float pz0 = ((float)vk + 0.5f) * VSZ + VMZ;

    unsigned long long acc0[16], acc1[16];
#pragma unroll
    for (int k = 0; k < 16; k++) { acc0[k] = 0ull; acc1[k] = 0ull; }

    int n = 0;
    if (lane == 0) { n = g_cnt[tile]; g_cnt[tile] = 0; }   // read + reset
    n = min(__shfl_sync(0xffffffffu, n, 0), TCAP);

    const float4*     gp4 = (const float4*)g_params;
    const ulonglong2* gf2 = (const ulonglong2*)feat;

    for (int base = 0; base < n; base += 32) {
        int m = min(32, n - base);
        int gi = 0;
        if (lane < m) gi = g_list[tile * TCAP + base + lane];

        // stage params: 8 candidates x 4 parts per pass
#pragma unroll
        for (int it = 0; it < 4; it++) {
            int c = it * 8 + (lane >> 2);
            int gidx = __shfl_sync(0xffffffffu, gi, c);
            if (c < m) s_par[wid][c][lane & 3] = gp4[gidx * 4 + (lane & 3)];
        }
        // stage features: 4 candidates x 8 parts per pass (16B = 2 f32x2 pairs)
#pragma unroll
        for (int it = 0; it < 8; it++) {
            int c = it * 4 + (lane >> 3);
            int gidx = __shfl_sync(0xffffffffu, gi, c);
            if (c < m) s_fea[wid][c][lane & 7] = gf2[gidx * 8 + (lane & 7)];
        }
        __syncwarp();

        for (int c = 0; c < m; c++) {
            float4 p0 = s_par[wid][c][0];
            float4 p1 = s_par[wid][c][1];
            float dx = px - p0.x, dy = py - p0.y;
            float dz0 = pz0 - p0.z, dz1 = dz0 + VSZ;
            bool inxy = (fabsf(dx) <= p1.x) && (fabsf(dy) <= p1.y);
            bool in0 = inxy && (fabsf(dz0) <= p1.z);
            bool in1 = inxy && (fabsf(dz1) <= p1.z);
            if (in0 || in1) {
                float4 p2 = s_par[wid][c][2];
                float4 p3 = s_par[wid][c][3];
                float mb = dx * (p2.x * dx + 2.f * p2.y * dy) + p2.w * dy * dy;
                float cz = 2.f * (p2.z * dx + p3.x * dy);
                float m0 = mb + dz0 * (p3.y * dz0 + cz);
                float m1 = mb + dz1 * (p3.y * dz1 + cz);
                float w0 = in0 ? p0.w * ex2(-m0) : 0.f;
                float w1 = in1 ? p0.w * ex2(-m1) : 0.f;
                unsigned long long w0p = pack2(w0);
                unsigned long long w1p = pack2(w1);
                const ulonglong2* f = s_fea[wid][c];
#pragma unroll
                for (int k = 0; k < 8; k++) {
                    ulonglong2 fv = f[k];
                    acc0[2 * k + 0] = fma2(w0p, fv.x, acc0[2 * k + 0]);
                    acc0[2 * k + 1] = fma2(w0p, fv.y, acc0[2 * k + 1]);
                    acc1[2 * k + 0] = fma2(w1p, fv.x, acc1[2 * k + 0]);
                    acc1[2 * k + 1] = fma2(w1p, fv.y, acc1[2 * k + 1]);
                }
            }
        }
        __syncwarp();
    }

    long long v = ((long long)vi * WN + vj) * DN + vk;
    ulonglong2* o0 = (ulonglong2*)(out + v * 32);
    ulonglong2* o1 = (ulonglong2*)(out + (v + 1) * 32);
#pragma unroll
    for (int k = 0; k < 8; k++)
        o0[k] = make_ulonglong2(acc0[2 * k + 0], acc0[2 * k + 1]);
#pragma unroll
    for (int k = 0; k < 8; k++)
        o1[k] = make_ulonglong2(acc1[2 * k + 0], acc1[2 * k + 1]);
}

// ---------------------------------------------------------------------------
extern "C" void kernel_launch(void* const* d_in, const int* in_sizes, int n_in,
                              void* d_out, int out_size) {
    const float* means = (const float*)d_in[0];
    const float* opac  = (const float*)d_in[1];
    const float* scl   = (const float*)d_in[2];
    const float* rot   = (const float*)d_in[3];
    const float* feat  = (const float*)d_in[4];
    float* out = (float*)d_out;

    k_prepbin<<<(NG * 32 + 255) / 256, 256>>>(means, opac, scl, rot);
    k_main<<<NTILES / 4, 128>>>(feat, out);
}

// round 9
// speedup vs baseline: 1.3448x; 1.3225x over previous
#include <cuda_runtime.h>
#include <cuda_bf16.h>

// ---------------------------------------------------------------------------
// GaussianVoxelizer round 7 = round-3 structure + packed f32x2 inner loop
//   (round-6 retry: feature staging now covers the FULL 32-float row:
//    8 ulonglong2 per gaussian, 16 packed accumulators per z-voxel)
// ---------------------------------------------------------------------------

#define NG      8192
#define HN      160
#define WN      160
#define DN      16
#define VSZ     0.4f
#define VMX     (-32.0f)
#define VMY     (-32.0f)
#define VMZ     (-1.0f)

#define TSH     3
#define TXN     (HN >> TSH)         // 20
#define TYN     (WN >> TSH)         // 20
#define TZN     (DN >> TSH)         // 2
#define NTILES  (TXN * TYN * TZN)   // 800

#define TCAP    256
#define CCHUNK  128
#define KEXP2   0.72134752044448170f   // 0.5 * log2(e)

__device__ float g_params[NG * 16];
__device__ int   g_cnt[NTILES];        // zero-init at load; k_main re-zeros
__device__ int   g_list[NTILES * TCAP];

__device__ __forceinline__ float ex2(float x) {
    float r;
    asm("ex2.approx.f32 %0, %1;" : "=f"(r) : "f"(x));
    return r;
}
__device__ __forceinline__ unsigned long long fma2(unsigned long long a,
                                                   unsigned long long b,
                                                   unsigned long long c) {
    unsigned long long d;
    asm("fma.rn.f32x2 %0, %1, %2, %3;" : "=l"(d) : "l"(a), "l"(b), "l"(c));
    return d;
}
__device__ __forceinline__ unsigned long long pack2(float x) {
    unsigned long long d;
    unsigned u = __float_as_uint(x);
    asm("mov.b64 %0, {%1, %1};" : "=l"(d) : "r"(u));
    return d;
}

// ---------------------------------------------------------------------------
__global__ void k_prepbin(const float* __restrict__ means,
                          const float* __restrict__ opac,
                          const float* __restrict__ scl,
                          const float* __restrict__ rot) {
    int t = blockIdx.x * blockDim.x + threadIdx.x;
    int g = t >> 5, lane = t & 31;
    if (g >= NG) return;

    unsigned range = 0xFFFFFFFFu;
    if (lane == 0) {
        float qw = rot[4 * g + 0], qx = rot[4 * g + 1];
        float qy = rot[4 * g + 2], qz = rot[4 * g + 3];
        float qn = rsqrtf(qw * qw + qx * qx + qy * qy + qz * qz);
        qw *= qn; qx *= qn; qy *= qn; qz *= qn;

        float r00 = 1.f - 2.f * (qy * qy + qz * qz);
        float r01 = 2.f * (qx * qy - qw * qz);
        float r02 = 2.f * (qx * qz + qw * qy);
        float r10 = 2.f * (qx * qy + qw * qz);
        float r11 = 1.f - 2.f * (qx * qx + qz * qz);
        float r12 = 2.f * (qy * qz - qw * qx);
        float r20 = 2.f * (qx * qz - qw * qy);
        float r21 = 2.f * (qy * qz + qw * qx);
        float r22 = 1.f - 2.f * (qx * qx + qy * qy);

        float s0 = scl[3 * g + 0], s1 = scl[3 * g + 1], s2 = scl[3 * g + 2];
        float v0 = s0 * s0, v1 = s1 * s1, v2 = s2 * s2;
        float a0 = 1.f / v0, a1 = 1.f / v1, a2 = 1.f / v2;

        float i00 = (r00 * r00 * a0 + r01 * r01 * a1 + r02 * r02 * a2) * KEXP2;
        float i01 = (r00 * r10 * a0 + r01 * r11 * a1 + r02 * r12 * a2) * KEXP2;
        float i02 = (r00 * r20 * a0 + r01 * r21 * a1 + r02 * r22 * a2) * KEXP2;
        float i11 = (r10 * r10 * a0 + r11 * r11 * a1 + r12 * r12 * a2) * KEXP2;
        float i12 = (r10 * r20 * a0 + r11 * r21 * a1 + r12 * r22 * a2) * KEXP2;
        float i22 = (r20 * r20 * a0 + r21 * r21 * a1 + r22 * r22 * a2) * KEXP2;

        float c00 = r00 * r00 * v0 + r01 * r01 * v1 + r02 * r02 * v2;
        float c11 = r10 * r10 * v0 + r11 * r11 * v1 + r12 * r12 * v2;
        float c22 = r20 * r20 * v0 + r21 * r21 * v1 + r22 * r22 * v2;
        float bx = 3.f * sqrtf(c00);
        float by = 3.f * sqrtf(c11);
        float bz = 3.f * sqrtf(c22);

        float mx = means[3 * g + 0], my = means[3 * g + 1], mz = means[3 * g + 2];
        float op = opac[g];

        float4* p4 = (float4*)&g_params[g * 16];
        p4[0] = make_float4(mx, my, mz, op);
        p4[1] = make_float4(bx, by, bz, 0.f);
        p4[2] = make_float4(i00, i01, i02, i11);
        p4[3] = make_float4(i12, i22, 0.f, 0.f);

        float mu[3] = { mx, my, mz };
        float bb[3] = { bx, by, bz };
        const float vmin[3] = { VMX, VMY, VMZ };
        const int nd[3] = { HN, WN, DN };
        int lo[3], hi[3];
        bool ok = true;
#pragma unroll
        for (int d = 0; d < 3; d++) {
            float l = (mu[d] - bb[d] - vmin[d]) / VSZ - 0.5f;
            float h = (mu[d] + bb[d] - vmin[d]) / VSZ - 0.5f;
            int i0 = (int)ceilf(l - 1e-3f);  if (i0 < 0) i0 = 0;
            int i1 = (int)floorf(h + 1e-3f); if (i1 > nd[d] - 1) i1 = nd[d] - 1;
            if (i0 > i1) ok = false;
            lo[d] = i0 >> TSH; hi[d] = i1 >> TSH;
        }
        if (ok)
            range = (unsigned)lo[0] | ((unsigned)hi[0] << 5)
                  | ((unsigned)lo[1] << 10) | ((unsigned)hi[1] << 15)
                  | ((unsigned)lo[2] << 20) | ((unsigned)hi[2] << 25);
    }
    range = __shfl_sync(0xffffffffu, range, 0);
    if (range == 0xFFFFFFFFu) return;

    int x0 = range & 31, x1 = (range >> 5) & 31;
    int y0 = (range >> 10) & 31, y1 = (range >> 15) & 31;
    int z0 = (range >> 20) & 31, z1 = (range >> 25) & 31;
    int nx = x1 - x0 + 1, ny = y1 - y0 + 1, nz = z1 - z0 + 1;
    if (lane >= nx * ny * nz) return;       // max span 3*3*2 = 18 <= 32
    int sz = lane % nz; int rem = lane / nz;
    int sy = rem % ny;  int sx = rem / ny;
    int tile = ((x0 + sx) * TYN + (y0 + sy)) * TZN + (z0 + sz);
    int pos = atomicAdd(&g_cnt[tile], 1);
    if (pos < TCAP) g_list[tile * TCAP + pos] = g;
}

// ---------------------------------------------------------------------------
__global__ __launch_bounds__(128)
void k_main(const float* __restrict__ feat, float* __restrict__ out) {
    __shared__ int        s_idx[CCHUNK];
    __shared__ float4     s_par[CCHUNK * 4];
    __shared__ ulonglong2 s_fea[CCHUNK * 8];   // 32 floats = 8 x ulonglong2
    __shared__ int        s_n;

    int bt = blockIdx.x;
    int tz = bt % TZN;
    int ty = (bt / TZN) % TYN;
    int tx = bt / (TZN * TYN);

    int tid = threadIdx.x;
    int lk = (tid & 1) << 2;       // z base: 0 or 4, thread owns 4 contiguous z
    int lj = (tid >> 1) & 7;
    int li = tid >> 4;

    int vi = (tx << TSH) + li;
    int vj = (ty << TSH) + lj;
    int vk = (tz << TSH) + lk;

    float px  = ((float)vi + 0.5f) * VSZ + VMX;
    float py  = ((float)vj + 0.5f) * VSZ + VMY;
    float pz0 = ((float)vk + 0.5f) * VSZ + VMZ;
    float pzc = pz0 + 1.5f * VSZ;          // center of 4-voxel z span

    int tile = (tx * TYN + ty) * TZN + tz;
    if (tid == 0) {
        int nn = g_cnt[tile];
        g_cnt[tile] = 0;                   // reset for next graph replay
        s_n = nn;
    }

    unsigned long long acc[4][16];
#pragma unroll
    for (int z = 0; z < 4; z++)
#pragma unroll
        for (int k = 0; k < 16; k++) acc[z][k] = 0ull;

    __syncthreads();
    int n = min(s_n, TCAP);

    const float4*     gp4 = (const float4*)g_params;
    const ulonglong2* gf2 = (const ulonglong2*)feat;

    for (int base = 0; base < n; base += CCHUNK) {
        int cnt = min(CCHUNK, n - base);
        __syncthreads();
        if (tid < cnt) s_idx[tid] = g_list[tile * TCAP + base + tid];
        __syncthreads();
        for (int u = tid; u < cnt * 4; u += 128) {
            int c = u >> 2, pc = u & 3;
            s_par[u] = gp4[s_idx[c] * 4 + pc];
        }
        for (int u = tid; u < cnt * 8; u += 128) {
            int c = u >> 3, pc = u & 7;
            s_fea[u] = gf2[s_idx[c] * 8 + pc];
        }
        __syncthreads();

        for (int c = 0; c < cnt; c++) {
            float4 p0 = s_par[c * 4 + 0];
            float4 p1 = s_par[c * 4 + 1];
            float dx = px - p0.x, dy = py - p0.y;
            float dzc = pzc - p0.z;
            if (fabsf(dx) <= p1.x && fabsf(dy) <= p1.y
                && fabsf(dzc) <= p1.z + 1.50001f * VSZ) {
                float4 p2 = s_par[c * 4 + 2];
                float4 p3 = s_par[c * 4 + 3];
                // quadratic pre-scaled by 0.5*log2(e)
                float mb = dx * (p2.x * dx + 2.f * p2.y * dy) + p2.w * dy * dy;
                float cz = 2.f * (p2.z * dx + p3.x * dy);
                unsigned long long w[4];
#pragma unroll
                for (int z = 0; z < 4; z++) {
                    float dz = (pz0 + (float)z * VSZ) - p0.z;
                    float m  = mb + dz * (p3.y * dz + cz);
                    bool in  = fabsf(dz) <= p1.z;
                    w[z] = pack2(in ? p0.w * ex2(-m) : 0.f);
                }
                const ulonglong2* f = &s_fea[c * 8];
#pragma unroll
                for (int k = 0; k < 8; k++) {
                    ulonglong2 fv = f[k];
#pragma unroll
                    for (int z = 0; z < 4; z++) {
                        acc[z][2 * k + 0] = fma2(w[z], fv.x, acc[z][2 * k + 0]);
                        acc[z][2 * k + 1] = fma2(w[z], fv.y, acc[z][2 * k + 1]);
                    }
                }
            }
        }
    }

    long long v = ((long long)vi * WN + vj) * DN + vk;
    float* o = out + v * 32;
#pragma unroll
    for (int z = 0; z < 4; z++) {
        ulonglong2* o2 = (ulonglong2*)(o + z * 32);
#pragma unroll
        for (int k = 0; k < 8; k++)
            o2[k] = make_ulonglong2(acc[z][2 * k + 0], acc[z][2 * k + 1]);
    }
}

// ---------------------------------------------------------------------------
extern "C" void kernel_launch(void* const* d_in, const int* in_sizes, int n_in,
                              void* d_out, int out_size) {
    const float* means = (const float*)d_in[0];
    const float* opac  = (const float*)d_in[1];
    const float* scl   = (const float*)d_in[2];
    const float* rot   = (const float*)d_in[3];
    const float* feat  = (const float*)d_in[4];
    float* out = (float*)d_out;

    k_prepbin<<<(NG * 32 + 255) / 256, 256>>>(means, opac, scl, rot);
    k_main<<<NTILES, 128>>>(feat, out);
}

// round 10
// speedup vs baseline: 1.5324x; 1.1395x over previous
#include <cuda_runtime.h>
#include <cuda_bf16.h>

// ---------------------------------------------------------------------------
// GaussianVoxelizer round 9: compact warp footprints for warp-level culling
//   k_prepbin: warp/gaussian, lane0 math, lane-per-tile-slot atomics (8^3 tiles)
//   k_main:    block(256) per 8x8x8 tile; each WARP owns a 4x4x4 voxel cell
//              (thread = 2 contiguous z voxels). Candidate FMA block is
//              branch-skipped warp-uniformly when no lane's voxels are in-box
//              (~58% of entries). Scalar FFMA (f32x2 reverted - RF-bank bound).
// ---------------------------------------------------------------------------

#define NG      8192
#define HN      160
#define WN      160
#define DN      16
#define VSZ     0.4f
#define VMX     (-32.0f)
#define VMY     (-32.0f)
#define VMZ     (-1.0f)

#define TSH     3
#define TXN     (HN >> TSH)         // 20
#define TYN     (WN >> TSH)         // 20
#define TZN     (DN >> TSH)         // 2
#define NTILES  (TXN * TYN * TZN)   // 800

#define TCAP    256
#define CCHUNK  128
#define KEXP2   0.72134752044448170f   // 0.5 * log2(e)

__device__ float g_params[NG * 16];
__device__ int   g_cnt[NTILES];        // zero-init at load; k_main re-zeros
__device__ int   g_list[NTILES * TCAP];

__device__ __forceinline__ float ex2(float x) {
    float r;
    asm("ex2.approx.f32 %0, %1;" : "=f"(r) : "f"(x));
    return r;
}

// ---------------------------------------------------------------------------
__global__ void k_prepbin(const float* __restrict__ means,
                          const float* __restrict__ opac,
                          const float* __restrict__ scl,
                          const float* __restrict__ rot) {
    int t = blockIdx.x * blockDim.x + threadIdx.x;
    int g = t >> 5, lane = t & 31;
    if (g >= NG) return;

    unsigned range = 0xFFFFFFFFu;
    if (lane == 0) {
        float qw = rot[4 * g + 0], qx = rot[4 * g + 1];
        float qy = rot[4 * g + 2], qz = rot[4 * g + 3];
        float qn = rsqrtf(qw * qw + qx * qx + qy * qy + qz * qz);
        qw *= qn; qx *= qn; qy *= qn; qz *= qn;

        float r00 = 1.f - 2.f * (qy * qy + qz * qz);
        float r01 = 2.f * (qx * qy - qw * qz);
        float r02 = 2.f * (qx * qz + qw * qy);
        float r10 = 2.f * (qx * qy + qw * qz);
        float r11 = 1.f - 2.f * (qx * qx + qz * qz);
        float r12 = 2.f * (qy * qz - qw * qx);
        float r20 = 2.f * (qx * qz - qw * qy);
        float r21 = 2.f * (qy * qz + qw * qx);
        float r22 = 1.f - 2.f * (qx * qx + qy * qy);

        float s0 = scl[3 * g + 0], s1 = scl[3 * g + 1], s2 = scl[3 * g + 2];
        float v0 = s0 * s0, v1 = s1 * s1, v2 = s2 * s2;
        float a0 = 1.f / v0, a1 = 1.f / v1, a2 = 1.f / v2;

        float i00 = (r00 * r00 * a0 + r01 * r01 * a1 + r02 * r02 * a2) * KEXP2;
        float i01 = (r00 * r10 * a0 + r01 * r11 * a1 + r02 * r12 * a2) * KEXP2;
        float i02 = (r00 * r20 * a0 + r01 * r21 * a1 + r02 * r22 * a2) * KEXP2;
        float i11 = (r10 * r10 * a0 + r11 * r11 * a1 + r12 * r12 * a2) * KEXP2;
        float i12 = (r10 * r20 * a0 + r11 * r21 * a1 + r12 * r22 * a2) * KEXP2;
        float i22 = (r20 * r20 * a0 + r21 * r21 * a1 + r22 * r22 * a2) * KEXP2;

        float c00 = r00 * r00 * v0 + r01 * r01 * v1 + r02 * r02 * v2;
        float c11 = r10 * r10 * v0 + r11 * r11 * v1 + r12 * r12 * v2;
        float c22 = r20 * r20 * v0 + r21 * r21 * v1 + r22 * r22 * v2;
        float bx = 3.f * sqrtf(c00);
        float by = 3.f * sqrtf(c11);
        float bz = 3.f * sqrtf(c22);

        float mx = means[3 * g + 0], my = means[3 * g + 1], mz = means[3 * g + 2];
        float op = opac[g];

        float4* p4 = (float4*)&g_params[g * 16];
        p4[0] = make_float4(mx, my, mz, op);
        p4[1] = make_float4(bx, by, bz, 0.f);
        p4[2] = make_float4(i00, i01, i02, i11);
        p4[3] = make_float4(i12, i22, 0.f, 0.f);

        float mu[3] = { mx, my, mz };
        float bb[3] = { bx, by, bz };
        const float vmin[3] = { VMX, VMY, VMZ };
        const int nd[3] = { HN, WN, DN };
        int lo[3], hi[3];
        bool ok = true;
#pragma unroll
        for (int d = 0; d < 3; d++) {
            float l = (mu[d] - bb[d] - vmin[d]) / VSZ - 0.5f;
            float h = (mu[d] + bb[d] - vmin[d]) / VSZ - 0.5f;
            int i0 = (int)ceilf(l - 1e-3f);  if (i0 < 0) i0 = 0;
            int i1 = (int)floorf(h + 1e-3f); if (i1 > nd[d] - 1) i1 = nd[d] - 1;
            if (i0 > i1) ok = false;
            lo[d] = i0 >> TSH; hi[d] = i1 >> TSH;
        }
        if (ok)
            range = (unsigned)lo[0] | ((unsigned)hi[0] << 5)
                  | ((unsigned)lo[1] << 10) | ((unsigned)hi[1] << 15)
                  | ((unsigned)lo[2] << 20) | ((unsigned)hi[2] << 25);
    }
    range = __shfl_sync(0xffffffffu, range, 0);
    if (range == 0xFFFFFFFFu) return;

    int x0 = range & 31, x1 = (range >> 5) & 31;
    int y0 = (range >> 10) & 31, y1 = (range >> 15) & 31;
    int z0 = (range >> 20) & 31, z1 = (range >> 25) & 31;
    int nx = x1 - x0 + 1, ny = y1 - y0 + 1, nz = z1 - z0 + 1;
    if (lane >= nx * ny * nz) return;       // max span 3*3*2 = 18 <= 32
    int sz = lane % nz; int rem = lane / nz;
    int sy = rem % ny;  int sx = rem / ny;
    int tile = ((x0 + sx) * TYN + (y0 + sy)) * TZN + (z0 + sz);
    int pos = atomicAdd(&g_cnt[tile], 1);
    if (pos < TCAP) g_list[tile * TCAP + pos] = g;
}

// ---------------------------------------------------------------------------
// block(256) per 8x8x8 tile; warp w owns 4x4x4 cell (wx,wy,wz half-splits);
// lane = (lx,ly,lz2), thread voxels (vi,vj,vk) and (vi,vj,vk+1).
__global__ __launch_bounds__(256, 2)
void k_main(const float* __restrict__ feat, float* __restrict__ out) {
    __shared__ int    s_idx[CCHUNK];
    __shared__ float4 s_par[CCHUNK * 4];
    __shared__ float4 s_fea[CCHUNK * 8];
    __shared__ int    s_n;

    int bt = blockIdx.x;
    int tz = bt % TZN;
    int ty = (bt / TZN) % TYN;
    int tx = bt / (TZN * TYN);

    int tid  = threadIdx.x;
    int w    = tid >> 5;
    int lane = tid & 31;
    int wx = w & 1, wy = (w >> 1) & 1, wz = (w >> 2) & 1;
    int lz2 = lane & 1;
    int ly  = (lane >> 1) & 3;
    int lx  = (lane >> 3) & 3;

    int vi = (tx << TSH) + (wx << 2) + lx;
    int vj = (ty << TSH) + (wy << 2) + ly;
    int vk = (tz << TSH) + (wz << 2) + (lz2 << 1);

    float px  = ((float)vi + 0.5f) * VSZ + VMX;
    float py  = ((float)vj + 0.5f) * VSZ + VMY;
    float pz0 = ((float)vk + 0.5f) * VSZ + VMZ;
    float pz1 = pz0 + VSZ;

    int tile = (tx * TYN + ty) * TZN + tz;
    if (tid == 0) {
        int nn = g_cnt[tile];
        g_cnt[tile] = 0;                   // reset for next graph replay
        s_n = nn;
    }

    float4 a0[8], a1[8];
#pragma unroll
    for (int r = 0; r < 8; r++) {
        a0[r] = make_float4(0.f, 0.f, 0.f, 0.f);
        a1[r] = make_float4(0.f, 0.f, 0.f, 0.f);
    }

    __syncthreads();
    int n = min(s_n, TCAP);

    const float4* gp4 = (const float4*)g_params;
    const float4* gf4 = (const float4*)feat;

    for (int base = 0; base < n; base += CCHUNK) {
        int cnt = min(CCHUNK, n - base);
        __syncthreads();
        if (tid < cnt) s_idx[tid] = g_list[tile * TCAP + base + tid];
        __syncthreads();
        for (int u = tid; u < cnt * 4; u += 256) {
            int c = u >> 2, pc = u & 3;
            s_par[u] = gp4[s_idx[c] * 4 + pc];
        }
        for (int u = tid; u < cnt * 8; u += 256) {
            int c = u >> 3, pc = u & 7;
            s_fea[u] = gf4[s_idx[c] * 8 + pc];
        }
        __syncthreads();

        for (int c = 0; c < cnt; c++) {
            float4 p0 = s_par[c * 4 + 0];
            float4 p1 = s_par[c * 4 + 1];
            float dx = px - p0.x, dy = py - p0.y;
            float dz0 = pz0 - p0.z, dz1 = pz1 - p0.z;
            bool inxy = (fabsf(dx) <= p1.x) && (fabsf(dy) <= p1.y);
            bool in0 = inxy && (fabsf(dz0) <= p1.z);
            bool in1 = inxy && (fabsf(dz1) <= p1.z);
            // warp-uniform skip when no lane of this compact cell is in-box
            if (in0 || in1) {
                float4 p2 = s_par[c * 4 + 2];
                float4 p3 = s_par[c * 4 + 3];
                // quadratic pre-scaled by 0.5*log2(e)
                float mb = dx * (p2.x * dx + 2.f * p2.y * dy) + p2.w * dy * dy;
                float cz = 2.f * (p2.z * dx + p3.x * dy);
                float m0 = mb + dz0 * (p3.y * dz0 + cz);
                float m1 = mb + dz1 * (p3.y * dz1 + cz);
                float w0 = in0 ? p0.w * ex2(-m0) : 0.f;
                float w1 = in1 ? p0.w * ex2(-m1) : 0.f;
                const float4* f = &s_fea[c * 8];
#pragma unroll
                for (int r = 0; r < 8; r++) {
                    float4 fv = f[r];
                    a0[r].x += w0 * fv.x; a0[r].y += w0 * fv.y;
                    a0[r].z += w0 * fv.z; a0[r].w += w0 * fv.w;
                    a1[r].x += w1 * fv.x; a1[r].y += w1 * fv.y;
                    a1[r].z += w1 * fv.z; a1[r].w += w1 * fv.w;
                }
            }
        }
    }

    // thread writes 2 contiguous voxels: 256B
    long long v = ((long long)vi * WN + vj) * DN + vk;
    float4* o0 = (float4*)(out + v * 32);
    float4* o1 = (float4*)(out + (v + 1) * 32);
#pragma unroll
    for (int r = 0; r < 8; r++) o0[r] = a0[r];
#pragma unroll
    for (int r = 0; r < 8; r++) o1[r] = a1[r];
}

// ---------------------------------------------------------------------------
extern "C" void kernel_launch(void* const* d_in, const int* in_sizes, int n_in,
                              void* d_out, int out_size) {
    const float* means = (const float*)d_in[0];
    const float* opac  = (const float*)d_in[1];
    const float* scl   = (const float*)d_in[2];
    const float* rot   = (const float*)d_in[3];
    const float* feat  = (const float*)d_in[4];
    float* out = (float*)d_out;

    k_prepbin<<<(NG * 32 + 255) / 256, 256>>>(means, opac, scl, rot);
    k_main<<<NTILES, 256>>>(feat, out);
}

// round 11
// speedup vs baseline: 1.7693x; 1.1546x over previous
#include <cuda_runtime.h>
#include <cuda_bf16.h>

// ---------------------------------------------------------------------------
// GaussianVoxelizer round 10: ballot-compacted survivor list, branchless core
//   k_prepbin: warp/gaussian, lane0 math, lane-per-tile-slot atomics (8^3 tiles)
//   k_main:    block(256) per 8x8x8 tile; warp owns a 4x4x4 cell.
//              Phase 1 per chunk: lane-parallel cell-vs-box test + ballot
//              compaction into per-warp survivor list.
//              Phase 2: straight-line (branch-free) weighted accumulate over
//              survivors; per-lane mask via select.
// ---------------------------------------------------------------------------

#define NG      8192
#define HN      160
#define WN      160
#define DN      16
#define VSZ     0.4f
#define VMX     (-32.0f)
#define VMY     (-32.0f)
#define VMZ     (-1.0f)

#define TSH     3
#define TXN     (HN >> TSH)         // 20
#define TYN     (WN >> TSH)         // 20
#define TZN     (DN >> TSH)         // 2
#define NTILES  (TXN * TYN * TZN)   // 800

#define TCAP    256
#define CCHUNK  128
#define KEXP2   0.72134752044448170f   // 0.5 * log2(e)
#define CHALF   (1.5f * VSZ + 1e-4f)   // cell half-extent (voxel centers) + eps

__device__ float g_params[NG * 16];
__device__ int   g_cnt[NTILES];        // zero-init at load; k_main re-zeros
__device__ int   g_list[NTILES * TCAP];

__device__ __forceinline__ float ex2(float x) {
    float r;
    asm("ex2.approx.f32 %0, %1;" : "=f"(r) : "f"(x));
    return r;
}

// ---------------------------------------------------------------------------
__global__ void k_prepbin(const float* __restrict__ means,
                          const float* __restrict__ opac,
                          const float* __restrict__ scl,
                          const float* __restrict__ rot) {
    int t = blockIdx.x * blockDim.x + threadIdx.x;
    int g = t >> 5, lane = t & 31;
    if (g >= NG) return;

    unsigned range = 0xFFFFFFFFu;
    if (lane == 0) {
        float qw = rot[4 * g + 0], qx = rot[4 * g + 1];
        float qy = rot[4 * g + 2], qz = rot[4 * g + 3];
        float qn = rsqrtf(qw * qw + qx * qx + qy * qy + qz * qz);
        qw *= qn; qx *= qn; qy *= qn; qz *= qn;

        float r00 = 1.f - 2.f * (qy * qy + qz * qz);
        float r01 = 2.f * (qx * qy - qw * qz);
        float r02 = 2.f * (qx * qz + qw * qy);
        float r10 = 2.f * (qx * qy + qw * qz);
        float r11 = 1.f - 2.f * (qx * qx + qz * qz);
        float r12 = 2.f * (qy * qz - qw * qx);
        float r20 = 2.f * (qx * qz - qw * qy);
        float r21 = 2.f * (qy * qz + qw * qx);
        float r22 = 1.f - 2.f * (qx * qx + qy * qy);

        float s0 = scl[3 * g + 0], s1 = scl[3 * g + 1], s2 = scl[3 * g + 2];
        float v0 = s0 * s0, v1 = s1 * s1, v2 = s2 * s2;
        float a0 = 1.f / v0, a1 = 1.f / v1, a2 = 1.f / v2;

        float i00 = (r00 * r00 * a0 + r01 * r01 * a1 + r02 * r02 * a2) * KEXP2;
        float i01 = (r00 * r10 * a0 + r01 * r11 * a1 + r02 * r12 * a2) * KEXP2;
        float i02 = (r00 * r20 * a0 + r01 * r21 * a1 + r02 * r22 * a2) * KEXP2;
        float i11 = (r10 * r10 * a0 + r11 * r11 * a1 + r12 * r12 * a2) * KEXP2;
        float i12 = (r10 * r20 * a0 + r11 * r21 * a1 + r12 * r22 * a2) * KEXP2;
        float i22 = (r20 * r20 * a0 + r21 * r21 * a1 + r22 * r22 * a2) * KEXP2;

        float c00 = r00 * r00 * v0 + r01 * r01 * v1 + r02 * r02 * v2;
        float c11 = r10 * r10 * v0 + r11 * r11 * v1 + r12 * r12 * v2;
        float c22 = r20 * r20 * v0 + r21 * r21 * v1 + r22 * r22 * v2;
        float bx = 3.f * sqrtf(c00);
        float by = 3.f * sqrtf(c11);
        float bz = 3.f * sqrtf(c22);

        float mx = means[3 * g + 0], my = means[3 * g + 1], mz = means[3 * g + 2];
        float op = opac[g];

        float4* p4 = (float4*)&g_params[g * 16];
        p4[0] = make_float4(mx, my, mz, op);
        p4[1] = make_float4(bx, by, bz, 0.f);
        p4[2] = make_float4(i00, i01, i02, i11);
        p4[3] = make_float4(i12, i22, 0.f, 0.f);

        float mu[3] = { mx, my, mz };
        float bb[3] = { bx, by, bz };
        const float vmin[3] = { VMX, VMY, VMZ };
        const int nd[3] = { HN, WN, DN };
        int lo[3], hi[3];
        bool ok = true;
#pragma unroll
        for (int d = 0; d < 3; d++) {
            float l = (mu[d] - bb[d] - vmin[d]) / VSZ - 0.5f;
            float h = (mu[d] + bb[d] - vmin[d]) / VSZ - 0.5f;
            int i0 = (int)ceilf(l - 1e-3f);  if (i0 < 0) i0 = 0;
            int i1 = (int)floorf(h + 1e-3f); if (i1 > nd[d] - 1) i1 = nd[d] - 1;
            if (i0 > i1) ok = false;
            lo[d] = i0 >> TSH; hi[d] = i1 >> TSH;
        }
        if (ok)
            range = (unsigned)lo[0] | ((unsigned)hi[0] << 5)
                  | ((unsigned)lo[1] << 10) | ((unsigned)hi[1] << 15)
                  | ((unsigned)lo[2] << 20) | ((unsigned)hi[2] << 25);
    }
    range = __shfl_sync(0xffffffffu, range, 0);
    if (range == 0xFFFFFFFFu) return;

    int x0 = range & 31, x1 = (range >> 5) & 31;
    int y0 = (range >> 10) & 31, y1 = (range >> 15) & 31;
    int z0 = (range >> 20) & 31, z1 = (range >> 25) & 31;
    int nx = x1 - x0 + 1, ny = y1 - y0 + 1, nz = z1 - z0 + 1;
    if (lane >= nx * ny * nz) return;       // max span 3*3*2 = 18 <= 32
    int sz = lane % nz; int rem = lane / nz;
    int sy = rem % ny;  int sx = rem / ny;
    int tile = ((x0 + sx) * TYN + (y0 + sy)) * TZN + (z0 + sz);
    int pos = atomicAdd(&g_cnt[tile], 1);
    if (pos < TCAP) g_list[tile * TCAP + pos] = g;
}

// ---------------------------------------------------------------------------
__global__ __launch_bounds__(256, 2)
void k_main(const float* __restrict__ feat, float* __restrict__ out) {
    __shared__ int    s_idx[CCHUNK];
    __shared__ float4 s_par[CCHUNK * 4];
    __shared__ float4 s_fea[CCHUNK * 8];
    __shared__ int    s_surv[8][CCHUNK];
    __shared__ int    s_n;

    int bt = blockIdx.x;
    int tz = bt % TZN;
    int ty = (bt / TZN) % TYN;
    int tx = bt / (TZN * TYN);

    int tid  = threadIdx.x;
    int w    = tid >> 5;
    int lane = tid & 31;
    int wx = w & 1, wy = (w >> 1) & 1, wz = (w >> 2) & 1;
    int lz2 = lane & 1;
    int ly  = (lane >> 1) & 3;
    int lx  = (lane >> 3) & 3;

    int vib = (tx << TSH) + (wx << 2);     // warp cell voxel bases
    int vjb = (ty << TSH) + (wy << 2);
    int vkb = (tz << TSH) + (wz << 2);

    int vi = vib + lx;
    int vj = vjb + ly;
    int vk = vkb + (lz2 << 1);

    float px  = ((float)vi + 0.5f) * VSZ + VMX;
    float py  = ((float)vj + 0.5f) * VSZ + VMY;
    float pz0 = ((float)vk + 0.5f) * VSZ + VMZ;
    float pz1 = pz0 + VSZ;

    // warp cell centers (voxel-center span is +/- 1.5*VSZ around these)
    float ccx = ((float)vib + 2.0f) * VSZ + VMX;
    float ccy = ((float)vjb + 2.0f) * VSZ + VMY;
    float ccz = ((float)vkb + 2.0f) * VSZ + VMZ;

    int tile = (tx * TYN + ty) * TZN + tz;
    if (tid == 0) {
        int nn = g_cnt[tile];
        g_cnt[tile] = 0;                   // reset for next graph replay
        s_n = nn;
    }

    float4 a0[8], a1[8];
#pragma unroll
    for (int r = 0; r < 8; r++) {
        a0[r] = make_float4(0.f, 0.f, 0.f, 0.f);
        a1[r] = make_float4(0.f, 0.f, 0.f, 0.f);
    }

    __syncthreads();
    int n = min(s_n, TCAP);

    const float4* gp4 = (const float4*)g_params;
    const float4* gf4 = (const float4*)feat;

    for (int base = 0; base < n; base += CCHUNK) {
        int cnt = min(CCHUNK, n - base);
        __syncthreads();
        if (tid < cnt) s_idx[tid] = g_list[tile * TCAP + base + tid];
        __syncthreads();
        for (int u = tid; u < cnt * 4; u += 256) {
            int c = u >> 2, pc = u & 3;
            s_par[u] = gp4[s_idx[c] * 4 + pc];
        }
        for (int u = tid; u < cnt * 8; u += 256) {
            int c = u >> 3, pc = u & 7;
            s_fea[u] = gf4[s_idx[c] * 8 + pc];
        }
        __syncthreads();

        // ---- phase 1: lane-parallel cell-vs-box test, ballot compaction ----
        int nsurv = 0;
        for (int b2 = 0; b2 < cnt; b2 += 32) {
            int c = b2 + lane;
            bool ov = false;
            if (c < cnt) {
                float4 p0 = s_par[c * 4 + 0];
                float4 p1 = s_par[c * 4 + 1];
                ov = (fabsf(ccx - p0.x) <= p1.x + CHALF)
                  && (fabsf(ccy - p0.y) <= p1.y + CHALF)
                  && (fabsf(ccz - p0.z) <= p1.z + CHALF);
            }
            unsigned m = __ballot_sync(0xffffffffu, ov);
            if (ov)
                s_surv[w][nsurv + __popc(m & ((1u << lane) - 1u))] = c;
            nsurv += __popc(m);
        }
        __syncwarp();

        // ---- phase 2: branch-free accumulate over survivors ----
        for (int s = 0; s < nsurv; s++) {
            int c = s_surv[w][s];
            float4 p0 = s_par[c * 4 + 0];
            float4 p1 = s_par[c * 4 + 1];
            float4 p2 = s_par[c * 4 + 2];
            float4 p3 = s_par[c * 4 + 3];
            float dx = px - p0.x, dy = py - p0.y;
            float dz0 = pz0 - p0.z, dz1 = pz1 - p0.z;
            bool inxy = (fabsf(dx) <= p1.x) && (fabsf(dy) <= p1.y);
            bool in0 = inxy && (fabsf(dz0) <= p1.z);
            bool in1 = inxy && (fabsf(dz1) <= p1.z);
            // quadratic pre-scaled by 0.5*log2(e)
            float mb = dx * (p2.x * dx + 2.f * p2.y * dy) + p2.w * dy * dy;
            float cz = 2.f * (p2.z * dx + p3.x * dy);
            float m0 = mb + dz0 * (p3.y * dz0 + cz);
            float m1 = mb + dz1 * (p3.y * dz1 + cz);
            float w0 = in0 ? p0.w * ex2(-m0) : 0.f;
            float w1 = in1 ? p0.w * ex2(-m1) : 0.f;
            const float4* f = &s_fea[c * 8];
#pragma unroll
            for (int r = 0; r < 8; r++) {
                float4 fv = f[r];
                a0[r].x += w0 * fv.x; a0[r].y += w0 * fv.y;
                a0[r].z += w0 * fv.z; a0[r].w += w0 * fv.w;
                a1[r].x += w1 * fv.x; a1[r].y += w1 * fv.y;
                a1[r].z += w1 * fv.z; a1[r].w += w1 * fv.w;
            }
        }
    }

    // thread writes 2 contiguous voxels: 256B
    long long v = ((long long)vi * WN + vj) * DN + vk;
    float4* o0 = (float4*)(out + v * 32);
    float4* o1 = (float4*)(out + (v + 1) * 32);
#pragma unroll
    for (int r = 0; r < 8; r++) o0[r] = a0[r];
#pragma unroll
    for (int r = 0; r < 8; r++) o1[r] = a1[r];
}

// ---------------------------------------------------------------------------
extern "C" void kernel_launch(void* const* d_in, const int* in_sizes, int n_in,
                              void* d_out, int out_size) {
    const float* means = (const float*)d_in[0];
    const float* opac  = (const float*)d_in[1];
    const float* scl   = (const float*)d_in[2];
    const float* rot   = (const float*)d_in[3];
    const float* feat  = (const float*)d_in[4];
    float* out = (float*)d_out;

    k_prepbin<<<(NG * 32 + 255) / 256, 256>>>(means, opac, scl, rot);
    k_main<<<NTILES, 256>>>(feat, out);
}